// round 17
// baseline (speedup 1.0000x reference)
#include <cuda_runtime.h>
#include <math.h>

#define BB 2
#define NN 256
#define FF 64
#define HH 4
#define HIDN 64
#define CC 256
#define KF 50
#define NODES (BB*NN)
#define CUTF 5.0f
#define PI_F 3.14159265358979f

// -------- scratch (device globals; no runtime allocation) --------
__device__ float g_Ain[NODES*KF];
__device__ float g_Bin[NODES*KF];
__device__ float g_P[NODES*HIDN];
__device__ float g_Q[NODES*HIDN];
__device__ unsigned int g_heb[(long)BB*NN*NN*32];  // h_e bf16 pairs (16 MB)
__device__ float g_attl[(long)BB*NN*NN*HH];        // att logits
__device__ float4 g_dx[(long)BB*NN*NN];            // (d, xhat)
__device__ float g_hesum[NODES*CC];
__device__ float g_cn[NODES*CC];
__device__ float g_dvp[NODES*8];                   // dv partials (2 halves)
// W_xmix head-decomposed A-frags: [half][w(8)][h(4)][kt(4)][lane(32)] uint4
__device__ uint4 g_WtF[8192];
// W_o1[128:179] and W_o2 in per-lane tf32 B-fragment layout
__device__ uint2 g_Wf[4096];

__device__ __forceinline__ float siluf(float v){ return v/(1.0f+expf(-v)); }
__device__ __forceinline__ float silu_fast(float v){
    return v * __fdividef(1.0f, 1.0f + __expf(-v));
}

__device__ __forceinline__ unsigned int pack_bf2(float lo, float hi){
    unsigned int r;
    asm("cvt.rn.bf16x2.f32 %0, %1, %2;" : "=r"(r) : "f"(hi), "f"(lo));
    return r;
}
__device__ __forceinline__ unsigned int smem_u32(const void* p){
    unsigned int a;
    asm("{ .reg .u64 t; cvta.to.shared.u64 t, %1; cvt.u32.u64 %0, t; }" : "=r"(a) : "l"(p));
    return a;
}
__device__ __forceinline__ float tanhfast(float x){
    float r; asm("tanh.approx.f32 %0, %1;" : "=f"(r) : "f"(x)); return r;
}
#define CVT_TF32(o, f) asm("cvt.rna.tf32.f32 %0, %1;" : "=r"(o) : "f"(f))
#define LDSM_X4(R, addr) \
    asm volatile("ldmatrix.sync.aligned.m8n8.x4.shared.b16 {%0,%1,%2,%3}, [%4];" \
        : "=r"((R)[0]),"=r"((R)[1]),"=r"((R)[2]),"=r"((R)[3]) : "r"(addr))
#define MMA16816(D, A, B0, B1) \
    asm volatile("mma.sync.aligned.m16n8k16.row.col.f32.bf16.bf16.f32 " \
        "{%0,%1,%2,%3}, {%4,%5,%6,%7}, {%8,%9}, {%0,%1,%2,%3};" \
        : "+f"((D)[0]),"+f"((D)[1]),"+f"((D)[2]),"+f"((D)[3]) \
        : "r"((A)[0]),"r"((A)[1]),"r"((A)[2]),"r"((A)[3]),"r"(B0),"r"(B1))
#define MMATF32(D, a0,a1,a2,a3, b0,b1) \
    asm volatile("mma.sync.aligned.m16n8k8.row.col.f32.tf32.tf32.f32 " \
        "{%0,%1,%2,%3}, {%4,%5,%6,%7}, {%8,%9}, {%0,%1,%2,%3};" \
        : "+f"((D)[0]),"+f"((D)[1]),"+f"((D)[2]),"+f"((D)[3]) \
        : "r"(a0),"r"(a1),"r"(a2),"r"(a3),"r"(b0),"r"(b1))

// -------- merged prep kernel --------
__global__ void k_prep(const float* __restrict__ h,
                       const float* __restrict__ W_in,
                       const float* __restrict__ W_o1,
                       const float* __restrict__ W_o2,
                       const float* __restrict__ W_xmix)
{
    int bid = blockIdx.x;
    int t = threadIdx.x;
    if (bid < NODES){
        __shared__ float sh[FF];
        int node = bid;
        if (t < FF) sh[t] = h[node*FF + t];
        __syncthreads();
        if (t < FF){
            float p = 0.f, q = 0.f;
            #pragma unroll 8
            for (int k = 0; k < FF; k++){
                float hv = sh[k];
                p = fmaf(hv, W_o1[k*HIDN + t], p);
                q = fmaf(hv, W_o1[(FF+k)*HIDN + t], q);
            }
            g_P[node*HIDN + t] = p;
            g_Q[node*HIDN + t] = q;
            if (t < KF){
                float a = 0.f, bv = 0.f;
                #pragma unroll 8
                for (int k = 0; k < FF; k++){
                    float hv = sh[k];
                    a  = fmaf(hv, W_in[k*KF + t], a);
                    bv = fmaf(hv, W_in[(FF+k)*KF + t], bv);
                }
                g_Ain[node*KF + t] = a;
                g_Bin[node*KF + t] = bv;
            }
        }
    } else if (bid < NODES + 32){
        int idx = (bid - NODES)*256 + t;     // 0..8191
        int lane = idx & 31;
        int kt = (idx >> 5) & 3;
        int hh = (idx >> 7) & 3;
        int w  = (idx >> 9) & 7;
        int half = (idx >> 12) & 1;
        int g = lane >> 2, tig = lane & 3;
        int r0 = (half*8 + w)*16 + g, r1 = r0 + 8;
        int f0 = kt*16 + tig*2;
        int f8 = f0 + 8;
        const float* W = W_xmix;
        uint4 f;
        f.x = pack_bf2(W[(4*f0+hh)*CC + r0],     W[(4*(f0+1)+hh)*CC + r0]);
        f.y = pack_bf2(W[(4*f0+hh)*CC + r1],     W[(4*(f0+1)+hh)*CC + r1]);
        f.z = pack_bf2(W[(4*f8+hh)*CC + r0],     W[(4*(f8+1)+hh)*CC + r0]);
        f.w = pack_bf2(W[(4*f8+hh)*CC + r1],     W[(4*(f8+1)+hh)*CC + r1]);
        g_WtF[idx] = f;
    } else {
        int idx = (bid - NODES - 32)*256 + t;   // 0..4095
        int lane = idx & 31;
        int nt = (idx >> 5) & 7;
        int kt = (idx >> 8) & 7;
        int m  = idx >> 11;
        int g = lane >> 2, tig = lane & 3;
        int k0 = kt*8 + tig, k1 = k0 + 4, n = nt*8 + g;
        float v0, v1;
        if (m == 0){
            v0 = (k0 <= 50) ? W_o1[(128 + k0)*HIDN + n] : 0.f;
            v1 = (k1 <= 50) ? W_o1[(128 + k1)*HIDN + n] : 0.f;
        } else {
            v0 = W_o2[k0*HIDN + n];
            v1 = W_o2[k1*HIDN + n];
        }
        unsigned u0, u1;
        CVT_TF32(u0, v0); CVT_TF32(u1, v1);
        g_Wf[m*2048 + (kt*8 + nt)*32 + lane] = make_uint2(u0, u1);
    }
}

// -------- K2: edge model via tf32 MMA (unchanged) --------
#define K2_OFF_A1   0u
#define K2_OFF_W1   32768u
#define K2_OFF_W2   49152u
#define K2_OFF_P    65536u
#define K2_OFF_Q    69888u
#define K2_OFF_AIN  72064u
#define K2_OFF_BIN  75392u
#define K2_OFF_WS   77056u
#define K2_OFF_BO1  78080u
#define K2_OFF_MEAN 78336u
#define K2_OFF_BETA 78544u
#define K2_OFF_BINV 78752u
#define K2_OFF_XI   78960u
#define K2_OFF_XJ   79088u
#define K2_OFF_BSEM 79344u
#define K2_SMEM     79360u

__global__ __launch_bounds__(256,2) void k2_edge(
    const float* __restrict__ x,
    const float* __restrict__ b_o1, const float* __restrict__ b_in,
    const float* __restrict__ means, const float* __restrict__ betas,
    const float* __restrict__ W_sem, const float* __restrict__ b_sem)
{
    extern __shared__ char smem[];
    int b  = blockIdx.z;
    int i0 = blockIdx.y*8, j0 = blockIdx.x*16;
    int t  = threadIdx.x;

    float* sP   = (float*)(smem + K2_OFF_P);
    float* sQ   = (float*)(smem + K2_OFF_Q);
    float* sAin = (float*)(smem + K2_OFF_AIN);
    float* sBin = (float*)(smem + K2_OFF_BIN);
    float4* sWs = (float4*)(smem + K2_OFF_WS);
    float* sBo1 = (float*)(smem + K2_OFF_BO1);
    float* sMean= (float*)(smem + K2_OFF_MEAN);
    float* sBeta= (float*)(smem + K2_OFF_BETA);
    float* sBinV= (float*)(smem + K2_OFF_BINV);
    float* sXi  = (float*)(smem + K2_OFF_XI);
    float* sXj  = (float*)(smem + K2_OFF_XJ);

    for (int idx = t; idx < 1024; idx += 256){
        ((uint4*)(smem + K2_OFF_W1))[idx] = ((const uint4*)g_Wf)[idx];
        ((uint4*)(smem + K2_OFF_W2))[idx] = ((const uint4*)g_Wf)[1024 + idx];
        sP[(idx >> 6)*68 + (idx & 63)] = g_P[(b*NN + j0 + (idx >> 6))*HIDN + (idx & 63)];
    }
    for (int idx = t; idx < 512; idx += 256)
        sQ[(idx >> 6)*68 + (idx & 63)] = g_Q[(b*NN + i0 + (idx >> 6))*HIDN + (idx & 63)];
    for (int idx = t; idx < 800; idx += 256){
        int r = idx/50, c = idx - r*50;
        sAin[r*52 + c] = g_Ain[(b*NN + j0 + r)*KF + c];
    }
    for (int idx = t; idx < 400; idx += 256){
        int r = idx/50, c = idx - r*50;
        sBin[r*52 + c] = g_Bin[(b*NN + i0 + r)*KF + c];
    }
    if (t < 64){
        sWs[t] = ((const float4*)W_sem)[t];
        sBo1[t] = b_o1[t];
    }
    if (t < 50){ sMean[t] = means[t]; sBeta[t] = betas[t]; sBinV[t] = b_in[t]; }
    if (t < 48){ int r = t/3, c = t - r*3; sXj[r*4 + c] = x[(b*NN + j0 + r)*3 + c]; }
    else if (t < 72){ int u = t - 48; int r = u/3, c = u - r*3; sXi[r*4 + c] = x[(b*NN + i0 + r)*3 + c]; }
    if (t == 0) *(float4*)(smem + K2_OFF_BSEM) = *(const float4*)b_sem;
    {
        uint4 z = make_uint4(0,0,0,0);
        for (int idx = t; idx < 512; idx += 256){
            int mt = idx >> 6, rest = idx & 63;
            ((uint4*)(smem + K2_OFF_A1))[(mt*8 + 6 + (rest >> 5))*32 + (rest & 31)] = z;
        }
    }
    __syncthreads();

    {
        int p = t & 127, bh = t >> 7;
        int il = p >> 4, jl = p & 15;
        float dxv = sXj[jl*4+0] - sXi[il*4+0];
        float dyv = sXj[jl*4+1] - sXi[il*4+1];
        float dzv = sXj[jl*4+2] - sXi[il*4+2];
        float d = sqrtf(dxv*dxv + dyv*dyv + dzv*dzv + 1e-5f);
        float cutv = (d < CUTF) ? 0.5f*(__cosf(d*(PI_F/CUTF)) + 1.0f) : 0.f;
        float em = __expf(-d);
        int gg = jl & 7, regRow = jl >> 3;
        unsigned base1 = (unsigned)(il*8)*512u + (unsigned)(gg*4)*16u + (unsigned)regRow*4u;
        if (bh){
            long pair = ((long)(b*NN + i0 + il))*NN + j0 + jl;
            float inv = 1.0f/(d + 1e-5f);
            g_dx[pair] = make_float4(d, dxv*inv, dyv*inv, dzv*inv);
        }
        int c0 = bh ? 26 : 0, c1 = bh ? 51 : 26;
        for (int c = c0; c < c1; c++){
            float val;
            if (c == 50) val = d;
            else {
                float h1 = sAin[jl*52 + c] + sBin[il*52 + c] + sBinV[c];
                float dm = em - sMean[c];
                val = cutv * __expf(-sBeta[c]*dm*dm) * h1;
            }
            unsigned r32; CVT_TF32(r32, val);
            unsigned addr = K2_OFF_A1 + base1 + (unsigned)((c >> 3))*512u
                          + (unsigned)(c & 3)*16u + (unsigned)((c >> 2) & 1)*8u;
            *(unsigned*)(smem + addr) = r32;
        }
    }
    __syncthreads();

    int lane = t & 31, warp = t >> 5;
    int g2 = lane >> 2, tig = lane & 3;
    const uint4* A1v = (const uint4*)(smem + K2_OFF_A1);
    const uint2* W1v = (const uint2*)(smem + K2_OFF_W1);
    const uint2* W2v = (const uint2*)(smem + K2_OFF_W2);

    float acc1[8][4];
    #pragma unroll
    for (int n = 0; n < 8; n++){ acc1[n][0]=acc1[n][1]=acc1[n][2]=acc1[n][3]=0.f; }
    #pragma unroll
    for (int kt = 0; kt < 8; kt++){
        uint4 aF = A1v[(warp*8 + kt)*32 + lane];
        #pragma unroll
        for (int nt = 0; nt < 8; nt++){
            uint2 bF = W1v[(kt*8 + nt)*32 + lane];
            MMATF32(acc1[nt], aF.x, aF.y, aF.z, aF.w, bF.x, bF.y);
        }
    }
    #pragma unroll
    for (int nt = 0; nt < 8; nt++){
        int f0 = nt*8 + tig*2;
        float q0 = sQ[warp*68 + f0]   + sBo1[f0];
        float q1 = sQ[warp*68 + f0+1] + sBo1[f0+1];
        acc1[nt][0] = silu_fast(acc1[nt][0] + sP[g2*68 + f0]       + q0);
        acc1[nt][1] = silu_fast(acc1[nt][1] + sP[g2*68 + f0+1]     + q1);
        acc1[nt][2] = silu_fast(acc1[nt][2] + sP[(g2+8)*68 + f0]   + q0);
        acc1[nt][3] = silu_fast(acc1[nt][3] + sP[(g2+8)*68 + f0+1] + q1);
    }
    float acc2[8][4];
    #pragma unroll
    for (int n = 0; n < 8; n++){ acc2[n][0]=acc2[n][1]=acc2[n][2]=acc2[n][3]=0.f; }
    int s0 = (lane & ~3) | (tig >> 1);
    int s1 = s0 + 2;
    bool odd = (tig & 1);
    #pragma unroll
    for (int kt = 0; kt < 8; kt++){
        float v0 = __shfl_sync(0xFFFFFFFFu, acc1[kt][0], s0);
        float v1 = __shfl_sync(0xFFFFFFFFu, acc1[kt][1], s0);
        float v2 = __shfl_sync(0xFFFFFFFFu, acc1[kt][2], s0);
        float v3 = __shfl_sync(0xFFFFFFFFu, acc1[kt][3], s0);
        float w0 = __shfl_sync(0xFFFFFFFFu, acc1[kt][0], s1);
        float w1 = __shfl_sync(0xFFFFFFFFu, acc1[kt][1], s1);
        float w2 = __shfl_sync(0xFFFFFFFFu, acc1[kt][2], s1);
        float w3 = __shfl_sync(0xFFFFFFFFu, acc1[kt][3], s1);
        unsigned a0, a1, a2, a3;
        CVT_TF32(a0, odd ? v1 : v0);
        CVT_TF32(a1, odd ? v3 : v2);
        CVT_TF32(a2, odd ? w1 : w0);
        CVT_TF32(a3, odd ? w3 : w2);
        #pragma unroll
        for (int nt = 0; nt < 8; nt++){
            uint2 bF = W2v[(kt*8 + nt)*32 + lane];
            MMATF32(acc2[nt], a0, a1, a2, a3, bF.x, bF.y);
        }
    }
    long rowPair0 = ((long)(b*NN + i0 + warp))*NN + j0 + g2;
    long rowPair1 = rowPair0 + 8;
    float l00=0.f,l01=0.f,l02=0.f,l03=0.f;
    float l10=0.f,l11=0.f,l12=0.f,l13=0.f;
    #pragma unroll
    for (int nt = 0; nt < 8; nt++){
        int f0 = nt*8 + tig*2;
        float h00 = acc2[nt][0], h01 = acc2[nt][1];
        float h10 = acc2[nt][2], h11 = acc2[nt][3];
        g_heb[rowPair0*32 + (f0 >> 1)] = pack_bf2(h00, h01);
        g_heb[rowPair1*32 + (f0 >> 1)] = pack_bf2(h10, h11);
        float4 ws0 = sWs[f0], ws1 = sWs[f0+1];
        l00 = fmaf(h00, ws0.x, fmaf(h01, ws1.x, l00));
        l01 = fmaf(h00, ws0.y, fmaf(h01, ws1.y, l01));
        l02 = fmaf(h00, ws0.z, fmaf(h01, ws1.z, l02));
        l03 = fmaf(h00, ws0.w, fmaf(h01, ws1.w, l03));
        l10 = fmaf(h10, ws0.x, fmaf(h11, ws1.x, l10));
        l11 = fmaf(h10, ws0.y, fmaf(h11, ws1.y, l11));
        l12 = fmaf(h10, ws0.z, fmaf(h11, ws1.z, l12));
        l13 = fmaf(h10, ws0.w, fmaf(h11, ws1.w, l13));
    }
    #define QRED(v) v += __shfl_xor_sync(0xFFFFFFFFu, v, 1); v += __shfl_xor_sync(0xFFFFFFFFu, v, 2);
    QRED(l00) QRED(l01) QRED(l02) QRED(l03)
    QRED(l10) QRED(l11) QRED(l12) QRED(l13)
    #undef QRED
    if (tig == 0){
        float4 bsem = *(float4*)(smem + K2_OFF_BSEM);
        float r0[4] = {l00 + bsem.x, l01 + bsem.y, l02 + bsem.z, l03 + bsem.w};
        float r1[4] = {l10 + bsem.x, l11 + bsem.y, l12 + bsem.z, l13 + bsem.w};
        #pragma unroll
        for (int hh = 0; hh < 4; hh++){
            r0[hh] = (r0[hh] > 0.f) ? r0[hh] : 2.0f*(__expf(0.5f*r0[hh]) - 1.0f);
            r1[hh] = (r1[hh] > 0.f) ? r1[hh] : 2.0f*(__expf(0.5f*r1[hh]) - 1.0f);
        }
        if (i0 + warp == j0 + g2)     { r0[0]-=1e5f; r0[1]-=1e5f; r0[2]-=1e5f; r0[3]-=1e5f; }
        if (i0 + warp == j0 + g2 + 8) { r1[0]-=1e5f; r1[1]-=1e5f; r1[2]-=1e5f; r1[3]-=1e5f; }
        *(float4*)&g_attl[rowPair0*HH] = make_float4(r0[0], r0[1], r0[2], r0[3]);
        *(float4*)&g_attl[rowPair1*HH] = make_float4(r1[0], r1[1], r1[2], r1[3]);
    }
}

// -------- K3: head-hoisted barrier-free HMMA xmix GEMM (unchanged) --------
#define HPITCH 144
#define OFF_A    0u
#define OFF_B    65536u
#define OFF_ATT  102400u
#define OFF_XH   106496u
#define OFF_RED  110592u
#define K3_SMEM  114688u

__global__ __launch_bounds__(256,2) void k3_attn(const float* __restrict__ W_vmix)
{
    extern __shared__ char smem[];
    unsigned int sbase = smem_u32(smem);
    float4* sAtt = (float4*)(smem + OFF_ATT);
    float4* sXh  = (float4*)(smem + OFF_XH);
    float4* sRed = (float4*)(smem + OFF_RED);
    const uint4* sA4 = (const uint4*)(smem + OFF_A);

    int node = blockIdx.x >> 1;
    int half = blockIdx.x & 1;
    int t = threadIdx.x;
    long base = ((long)node)*NN;

    {
        const uint4* src = g_WtF + half*4096;
        uint4* dst = (uint4*)(smem + OFF_A);
        for (int idx = t; idx < 4096; idx += 256) dst[idx] = src[idx];
    }
    {
        for (int idx = t; idx < 2048; idx += 256){
            int row = idx >> 3, ch = idx & 7;
            *(uint4*)(smem + OFF_B + row*HPITCH + ch*16)
                = *(const uint4*)(g_heb + (base + row)*32 + ch*4);
        }
    }

    float4 l = *(const float4*)&g_attl[(base + t)*HH];
    sRed[t] = l;
    sXh[t] = g_dx[base + t];
    __syncthreads();
    for (int s = 128; s; s >>= 1){
        if (t < s){
            float4 o2 = sRed[t+s]; float4 m = sRed[t];
            m.x = fmaxf(m.x,o2.x); m.y = fmaxf(m.y,o2.y);
            m.z = fmaxf(m.z,o2.z); m.w = fmaxf(m.w,o2.w);
            sRed[t] = m;
        }
        __syncthreads();
    }
    float4 mx = sRed[0];
    __syncthreads();
    float4 e = make_float4(expf(l.x-mx.x), expf(l.y-mx.y), expf(l.z-mx.z), expf(l.w-mx.w));
    sRed[t] = e;
    __syncthreads();
    for (int s = 128; s; s >>= 1){
        if (t < s){
            float4 o2 = sRed[t+s]; float4 m = sRed[t];
            m.x += o2.x; m.y += o2.y; m.z += o2.z; m.w += o2.w;
            sRed[t] = m;
        }
        __syncthreads();
    }
    float4 sm = sRed[0];
    __syncthreads();
    float4 att = make_float4(e.x/sm.x, e.y/sm.y, e.z/sm.z, e.w/sm.w);
    sAtt[t] = att;
    __syncthreads();

    if (half == 0){
        int f = t & 63, q = t >> 6;
        int sh = (f & 1)*16;
        const unsigned int* hb = g_heb + (base + q*64)*32 + (f >> 1);
        float s0=0.f, s1=0.f, s2=0.f, s3=0.f;
        #pragma unroll 4
        for (int jj = 0; jj < 64; jj++){
            unsigned int u = hb[jj*32];
            float hev = __uint_as_float(((u >> sh) & 0xFFFFu) << 16);
            float4 a4 = sAtt[q*64 + jj];
            s0 = fmaf(hev, a4.x, s0); s1 = fmaf(hev, a4.y, s1);
            s2 = fmaf(hev, a4.z, s2); s3 = fmaf(hev, a4.w, s3);
        }
        sRed[t] = make_float4(s0, s1, s2, s3);
    }
    __syncthreads();
    if (half == 0){
        int f = t >> 2, hh2 = t & 3;
        float s = ((const float*)&sRed[f])[hh2]
                + ((const float*)&sRed[64+f])[hh2]
                + ((const float*)&sRed[128+f])[hh2]
                + ((const float*)&sRed[192+f])[hh2];
        g_hesum[node*CC + t] = s;
    }
    __syncthreads();

    int lane = t & 31, warp = t >> 5;
    int g = lane >> 2, tig = lane & 3;
    unsigned int bBase4 = sbase + OFF_B + (unsigned)((lane & 7))*HPITCH
                        + (unsigned)(((lane >> 3) & 1)*16)
                        + (unsigned)(((lane >> 4) & 1)*(8*HPITCH));

    uint4 aC[4][4];
    #pragma unroll
    for (int hh = 0; hh < 4; hh++)
        #pragma unroll
        for (int kt = 0; kt < 4; kt++)
            aC[hh][kt] = sA4[(warp*16 + hh*4 + kt)*32 + lane];

    float cs[2][3];
    cs[0][0]=cs[0][1]=cs[0][2]=cs[1][0]=cs[1][1]=cs[1][2]=0.f;

    for (int jb = 0; jb < 4; jb++){
        unsigned int bJB = bBase4 + (unsigned)(jb*64*HPITCH);
        #pragma unroll
        for (int np = 0; np < 4; np++){
            float Gn[4][8];
            #pragma unroll
            for (int hh = 0; hh < 4; hh++)
                #pragma unroll
                for (int q = 0; q < 8; q++) Gn[hh][q] = 0.f;

            #pragma unroll
            for (int kt = 0; kt < 4; kt++){
                unsigned int bfr[4];
                LDSM_X4(bfr, bJB + (unsigned)(np*16*HPITCH + kt*32));
                #pragma unroll
                for (int hh = 0; hh < 4; hh++){
                    MMA16816(Gn[hh],     (unsigned int*)&aC[hh][kt], bfr[0], bfr[1]);
                    MMA16816(Gn[hh] + 4, (unsigned int*)&aC[hh][kt], bfr[2], bfr[3]);
                }
            }
            #pragma unroll
            for (int s = 0; s < 2; s++){
                int j0 = jb*64 + (np*2 + s)*8 + tig*2;
                float4 aA = sAtt[j0], aB = sAtt[j0+1];
                float f0 = fmaf(aA.x, Gn[0][s*4+0], fmaf(aA.y, Gn[1][s*4+0],
                           fmaf(aA.z, Gn[2][s*4+0], aA.w*Gn[3][s*4+0])));
                float f1 = fmaf(aB.x, Gn[0][s*4+1], fmaf(aB.y, Gn[1][s*4+1],
                           fmaf(aB.z, Gn[2][s*4+1], aB.w*Gn[3][s*4+1])));
                float f2 = fmaf(aA.x, Gn[0][s*4+2], fmaf(aA.y, Gn[1][s*4+2],
                           fmaf(aA.z, Gn[2][s*4+2], aA.w*Gn[3][s*4+2])));
                float f3 = fmaf(aB.x, Gn[0][s*4+3], fmaf(aB.y, Gn[1][s*4+3],
                           fmaf(aB.z, Gn[2][s*4+3], aB.w*Gn[3][s*4+3])));
                float t0 = tanhfast(f0);
                float t1 = tanhfast(f1);
                float t2 = tanhfast(f2);
                float t3 = tanhfast(f3);
                float4 x0 = sXh[j0], x1 = sXh[j0+1];
                cs[0][0] = fmaf(t0, x0.y, fmaf(t1, x1.y, cs[0][0]));
                cs[0][1] = fmaf(t0, x0.z, fmaf(t1, x1.z, cs[0][1]));
                cs[0][2] = fmaf(t0, x0.w, fmaf(t1, x1.w, cs[0][2]));
                cs[1][0] = fmaf(t2, x0.y, fmaf(t3, x1.y, cs[1][0]));
                cs[1][1] = fmaf(t2, x0.z, fmaf(t3, x1.z, cs[1][1]));
                cs[1][2] = fmaf(t2, x0.w, fmaf(t3, x1.w, cs[1][2]));
            }
        }
    }

    #pragma unroll
    for (int r = 0; r < 2; r++)
        #pragma unroll
        for (int q = 0; q < 3; q++){
            float v = cs[r][q];
            v += __shfl_xor_sync(0xFFFFFFFFu, v, 1);
            v += __shfl_xor_sync(0xFFFFFFFFu, v, 2);
            cs[r][q] = v;
        }

    const float invn = 1.0f/(float)NN;
    float pd0 = 0.f, pd1 = 0.f, pd2 = 0.f;
    if (tig == 0){
        #pragma unroll
        for (int r = 0; r < 2; r++){
            int cpr = half*128 + warp*16 + r*8 + g;
            float a  = cs[r][0]*invn;
            float b2 = cs[r][1]*invn;
            float c2 = cs[r][2]*invn;
            g_cn[node*CC + cpr] = a*a + b2*b2 + c2*c2;
            float wv = W_vmix[cpr];
            pd0 = fmaf(a, wv, pd0);
            pd1 = fmaf(b2, wv, pd1);
            pd2 = fmaf(c2, wv, pd2);
        }
    }
    __syncthreads();
    sRed[t] = make_float4(pd0, pd1, pd2, 0.f);
    __syncthreads();
    for (int s = 128; s; s >>= 1){
        if (t < s){
            float4 o2 = sRed[t+s]; float4 m2 = sRed[t];
            m2.x += o2.x; m2.y += o2.y; m2.z += o2.z;
            sRed[t] = m2;
        }
        __syncthreads();
    }
    if (t == 0){
        float4 r = sRed[0];
        g_dvp[node*8 + half*4 + 0] = r.x;
        g_dvp[node*8 + half*4 + 1] = r.y;
        g_dvp[node*8 + half*4 + 2] = r.z;
    }
}

// -------- K4: persistent node MLPs, weights staged in SMEM --------
#define W4_P1  0u         // 256*64*4 = 65536
#define W4_N1  65536u     // 384*64*4 = 98304 -> 163840
#define W4_P2  163840u    // 16384 -> 180224
#define W4_N2  180224u    // 16384 -> 196608
#define W4_V1  196608u    // 16384 -> 212992
#define W4_BP1 212992u
#define W4_BP2 213248u
#define W4_BN1 213504u
#define W4_BN2 213760u
#define W4_BV1 214016u
#define W4_WV2 214272u
#define W4_IN  214528u    // float[384] -> 216064
#define W4_CN  216064u    // float[256] -> 217088
#define W4_ACC 217088u    // float[256] -> 218112
#define W4_X   218112u    // float[64] -> 218368
#define W4_Y   218368u    // float[64] -> 218624
#define W4_FIN 218624u
#define K4_SMEM 218752u
#define K4_GRID 128

__global__ __launch_bounds__(256,1) void k4_node(
    const float* __restrict__ h, const float* __restrict__ x, const float* __restrict__ v,
    const float* __restrict__ W_p1, const float* __restrict__ b_p1,
    const float* __restrict__ W_p2, const float* __restrict__ b_p2,
    const float* __restrict__ W_n1, const float* __restrict__ b_n1,
    const float* __restrict__ W_n2, const float* __restrict__ b_n2,
    const float* __restrict__ W_v1, const float* __restrict__ b_v1,
    const float* __restrict__ W_v2, float* __restrict__ out)
{
    extern __shared__ char smem[];
    int t = threadIdx.x;
    int to = t & 63, ko = t >> 6;
    float* sWp1 = (float*)(smem + W4_P1);
    float* sWn1 = (float*)(smem + W4_N1);
    float* sWp2 = (float*)(smem + W4_P2);
    float* sWn2 = (float*)(smem + W4_N2);
    float* sWv1 = (float*)(smem + W4_V1);
    float* sIn  = (float*)(smem + W4_IN);
    float* sCn  = (float*)(smem + W4_CN);
    float* sAcc = (float*)(smem + W4_ACC);
    float* sX   = (float*)(smem + W4_X);
    float* sY   = (float*)(smem + W4_Y);
    float* sFin = (float*)(smem + W4_FIN);

    // ---- stage all weights once ----
    for (int idx = t; idx < 4096; idx += 256)
        ((uint4*)sWp1)[idx] = ((const uint4*)W_p1)[idx];
    for (int idx = t; idx < 6144; idx += 256)
        ((uint4*)sWn1)[idx] = ((const uint4*)W_n1)[idx];
    for (int idx = t; idx < 1024; idx += 256){
        ((uint4*)sWp2)[idx] = ((const uint4*)W_p2)[idx];
        ((uint4*)sWn2)[idx] = ((const uint4*)W_n2)[idx];
        ((uint4*)sWv1)[idx] = ((const uint4*)W_v1)[idx];
    }
    if (t < 64){
        ((float*)(smem + W4_BP1))[t] = b_p1[t];
        ((float*)(smem + W4_BP2))[t] = b_p2[t];
        ((float*)(smem + W4_BN1))[t] = b_n1[t];
        ((float*)(smem + W4_BN2))[t] = b_n2[t];
        ((float*)(smem + W4_BV1))[t] = b_v1[t];
        ((float*)(smem + W4_WV2))[t] = W_v2[t];
    }
    __syncthreads();

    for (int node = blockIdx.x; node < NODES; node += K4_GRID){
        if (t < 64) sIn[t] = h[node*FF + t];
        for (int k = t; k < CC; k += 256){
            sIn[64 + k] = g_hesum[node*CC + k];
            sCn[k] = g_cn[node*CC + k];
        }
        __syncthreads();

        // p1: 256 -> 64
        {
            float acc = 0.f;
            int k0 = ko*64;
            #pragma unroll 8
            for (int k = 0; k < 64; k++)
                acc = fmaf(sCn[k0+k], sWp1[(k0+k)*HIDN + to], acc);
            sAcc[t] = acc;
        }
        __syncthreads();
        if (ko == 0)
            sX[to] = siluf(((float*)(smem + W4_BP1))[to] + sAcc[to] + sAcc[64+to] + sAcc[128+to] + sAcc[192+to]);
        __syncthreads();
        // p2: 64 -> 64
        {
            float acc = 0.f;
            int k0 = ko*16;
            #pragma unroll
            for (int k = 0; k < 16; k++)
                acc = fmaf(sX[k0+k], sWp2[(k0+k)*HIDN + to], acc);
            sAcc[t] = acc;
        }
        __syncthreads();
        if (ko == 0)
            sIn[320 + to] = siluf(((float*)(smem + W4_BP2))[to] + sAcc[to] + sAcc[64+to] + sAcc[128+to] + sAcc[192+to]);
        __syncthreads();
        // n1: 384 -> 64
        {
            float acc = 0.f;
            int k0 = ko*96;
            #pragma unroll 8
            for (int k = 0; k < 96; k++)
                acc = fmaf(sIn[k0+k], sWn1[(k0+k)*HIDN + to], acc);
            sAcc[t] = acc;
        }
        __syncthreads();
        if (ko == 0)
            sX[to] = siluf(((float*)(smem + W4_BN1))[to] + sAcc[to] + sAcc[64+to] + sAcc[128+to] + sAcc[192+to]);
        __syncthreads();
        // n2: 64 -> 64, residual
        {
            float acc = 0.f;
            int k0 = ko*16;
            #pragma unroll
            for (int k = 0; k < 16; k++)
                acc = fmaf(sX[k0+k], sWn2[(k0+k)*HIDN + to], acc);
            sAcc[t] = acc;
        }
        __syncthreads();
        if (ko == 0){
            float hn = sIn[to] + siluf(((float*)(smem + W4_BN2))[to] + sAcc[to] + sAcc[64+to] + sAcc[128+to] + sAcc[192+to]);
            sY[to] = hn;
            out[node*FF + to] = hn;
        }
        __syncthreads();
        // v1: 64 -> 64
        {
            float acc = 0.f;
            int k0 = ko*16;
            #pragma unroll
            for (int k = 0; k < 16; k++)
                acc = fmaf(sY[k0+k], sWv1[(k0+k)*HIDN + to], acc);
            sAcc[t] = acc;
        }
        __syncthreads();
        if (ko == 0)
            sX[to] = siluf(((float*)(smem + W4_BV1))[to] + sAcc[to] + sAcc[64+to] + sAcc[128+to] + sAcc[192+to]) * ((float*)(smem + W4_WV2))[to];
        __syncthreads();
        if (t < 32){
            float s = sX[t] + sX[t+32];
            #pragma unroll
            for (int o2 = 16; o2; o2 >>= 1)
                s += __shfl_xor_sync(0xFFFFFFFFu, s, o2);
            if (t == 0) sFin[0] = s;
        }
        __syncthreads();
        if (t < 3){
            float vs = 2.0f/(1.0f + expf(-sFin[0]));
            float vn = g_dvp[node*8 + t] + g_dvp[node*8 + 4 + t] + vs * v[node*3 + t];
            out[NODES*FF + node*3 + t]            = x[node*3 + t] + vn;
            out[NODES*FF + NODES*3 + node*3 + t]  = vn;
        }
        __syncthreads();
    }
}

extern "C" void kernel_launch(void* const* d_in, const int* in_sizes, int n_in,
                              void* d_out, int out_size)
{
    const float* h      = (const float*)d_in[0];
    const float* x      = (const float*)d_in[1];
    const float* v      = (const float*)d_in[2];
    const float* W_in   = (const float*)d_in[3];
    const float* b_in   = (const float*)d_in[4];
    const float* means  = (const float*)d_in[5];
    const float* betas  = (const float*)d_in[6];
    const float* W_o1   = (const float*)d_in[7];
    const float* b_o1   = (const float*)d_in[8];
    const float* W_o2   = (const float*)d_in[9];
    const float* b_o2   = (const float*)d_in[10];
    const float* W_sem  = (const float*)d_in[11];
    const float* b_sem  = (const float*)d_in[12];
    const float* W_xmix = (const float*)d_in[13];
    const float* W_p1   = (const float*)d_in[14];
    const float* b_p1   = (const float*)d_in[15];
    const float* W_p2   = (const float*)d_in[16];
    const float* b_p2   = (const float*)d_in[17];
    const float* W_n1   = (const float*)d_in[18];
    const float* b_n1   = (const float*)d_in[19];
    const float* W_n2   = (const float*)d_in[20];
    const float* b_n2   = (const float*)d_in[21];
    const float* W_v1   = (const float*)d_in[22];
    const float* b_v1   = (const float*)d_in[23];
    const float* W_v2   = (const float*)d_in[24];
    const float* W_vmix = (const float*)d_in[25];
    float* out = (float*)d_out;

    static int smem_set = 0;
    if (!smem_set){
        cudaFuncSetAttribute(k3_attn, cudaFuncAttributeMaxDynamicSharedMemorySize, K3_SMEM);
        cudaFuncSetAttribute(k2_edge, cudaFuncAttributeMaxDynamicSharedMemorySize, K2_SMEM);
        cudaFuncSetAttribute(k4_node, cudaFuncAttributeMaxDynamicSharedMemorySize, K4_SMEM);
        smem_set = 1;
    }

    k_prep<<<NODES + 48, 256>>>(h, W_in, W_o1, W_o2, W_xmix);
    dim3 g2(NN/16, NN/8, BB);
    k2_edge<<<g2, 256, K2_SMEM>>>(x, b_o1, b_in, means, betas, W_sem, b_sem);
    k3_attn<<<NODES*2, 256, K3_SMEM>>>(W_vmix);
    k4_node<<<K4_GRID, 256, K4_SMEM>>>(h, x, v, W_p1, b_p1, W_p2, b_p2,
                                       W_n1, b_n1, W_n2, b_n2, W_v1, b_v1, W_v2, out);
}